// round 2
// baseline (speedup 1.0000x reference)
#include <cuda_runtime.h>
#include <cstdint>

// Problem constants
#define B_ 4
#define H_ 16
#define S_ 1024
#define D_ 64

// 1 => JAX jax_threefry_partitionable=True (default since JAX 0.4.36):
//      bits[i] = x0^x1 of threefry((0,42),(0,i))
// 0 => legacy path: counters split in halves, bits[i]=out0 (i<n/2) / out1
#define JAX_PARTITIONABLE 1

#define NTOT   ((size_t)B_ * H_ * S_ * S_)   // 2^26 mask bits
#define NWORDS (NTOT / 32)                   // 2^21 uint32 words

__device__ uint32_t g_mask[NWORDS];          // 8 MB scratch (static, allowed)

// ---------------------------------------------------------------------------
// Threefry-2x32 (20 rounds), matches jax/_src/prng.py
// ---------------------------------------------------------------------------
__device__ __forceinline__ void threefry2x32(uint32_t k0, uint32_t k1,
                                             uint32_t& x0, uint32_t& x1) {
    uint32_t ks2 = 0x1BD11BDAu ^ k0 ^ k1;
    x0 += k0; x1 += k1;
#define TF_RND(r) { x0 += x1; x1 = __funnelshift_l(x1, x1, (r)); x1 ^= x0; }
    TF_RND(13) TF_RND(15) TF_RND(26) TF_RND(6)
    x0 += k1;  x1 += ks2 + 1u;
    TF_RND(17) TF_RND(29) TF_RND(16) TF_RND(24)
    x0 += ks2; x1 += k0 + 2u;
    TF_RND(13) TF_RND(15) TF_RND(26) TF_RND(6)
    x0 += k0;  x1 += k1 + 3u;
    TF_RND(17) TF_RND(29) TF_RND(16) TF_RND(24)
    x0 += k1;  x1 += ks2 + 4u;
    TF_RND(13) TF_RND(15) TF_RND(26) TF_RND(6)
    x0 += ks2; x1 += k0 + 5u;
#undef TF_RND
}

// keep  <=>  uniform(bits) < 0.9f  <=>  (bits>>9) < 0x733333  <=>  bits < 0xE6666600
#define KEEP_THRESH 0xE6666600u

// ---------------------------------------------------------------------------
// Mask precompute: one 32-bit mask word per thread
// ---------------------------------------------------------------------------
__global__ void __launch_bounds__(256) mask_kernel() {
    uint32_t t = blockIdx.x * 256u + threadIdx.x;       // [0, NWORDS) or [0, NWORDS/2)
#if JAX_PARTITIONABLE
    uint32_t base = t * 32u;
    uint32_t w = 0u;
#pragma unroll 4
    for (int b = 0; b < 32; b++) {
        uint32_t x0 = 0u, x1 = base + (uint32_t)b;      // (hi, lo) of 64-bit iota
        threefry2x32(0u, 42u, x0, x1);
        uint32_t bits = x0 ^ x1;
        w |= (bits < KEEP_THRESH ? 1u : 0u) << b;
    }
    g_mask[t] = w;
#else
    // legacy: counters [0..n) split into halves; (out0,out1)=threefry(key, i, i+n/2)
    const uint32_t HALF = (uint32_t)(NTOT / 2);
    uint32_t base = t * 32u;                            // t in [0, NWORDS/2)
    uint32_t w0 = 0u, w1 = 0u;
#pragma unroll 4
    for (int b = 0; b < 32; b++) {
        uint32_t x0 = base + (uint32_t)b;
        uint32_t x1 = x0 + HALF;
        threefry2x32(0u, 42u, x0, x1);
        w0 |= (x0 < KEEP_THRESH ? 1u : 0u) << b;
        w1 |= (x1 < KEEP_THRESH ? 1u : 0u) << b;
    }
    g_mask[t] = w0;
    g_mask[t + NWORDS / 2] = w1;
#endif
}

// ---------------------------------------------------------------------------
// Flash attention, fp32, 64x64 tiles, 256 threads, 4x4 strided micro-tiles
// ---------------------------------------------------------------------------
#define QT 64
#define STRIDE 68        // padded float stride (conflict mitigation + 16B align)
#define ST4 17           // STRIDE/4

__global__ void __launch_bounds__(256, 2)
attn_kernel(const float* __restrict__ Q, const float* __restrict__ K,
            const float* __restrict__ V, const uint32_t* __restrict__ scale_ptr,
            float* __restrict__ O) {
    extern __shared__ float sm[];
    float* Qs = sm;                      // QT x STRIDE (pre-scaled by scale_factor)
    float* Ks = sm + QT * STRIDE;
    float* Vs = sm + 2 * QT * STRIDE;
    float* Ps = sm + 3 * QT * STRIDE;

    const int tid = threadIdx.x;
    const int bh  = blockIdx.y;          // b*H + h
    const int qb  = blockIdx.x * QT;

    // scale_factor may arrive as int32(8) or float32(8.0); decode either
    uint32_t sw = *scale_ptr;
    float scale = (sw & 0x7f800000u) ? __uint_as_float(sw) : (float)(int)sw;

    const float* Qp = Q + ((size_t)bh * S_ + qb) * D_;
    const float* Kp = K + (size_t)bh * S_ * D_;
    const float* Vp = V + (size_t)bh * S_ * D_;

    // Load Q tile (scaled)
    for (int e = tid; e < QT * D_ / 4; e += 256) {
        int r = e >> 4, c = e & 15;
        float4 v = reinterpret_cast<const float4*>(Qp)[e];
        v.x *= scale; v.y *= scale; v.z *= scale; v.w *= scale;
        *reinterpret_cast<float4*>(&Qs[r * STRIDE + c * 4]) = v;
    }

    const int ty = tid >> 4;             // 0..15 (row group)
    const int tx = tid & 15;             // 0..15 (col group)

    float acc[4][4];
    float mrow[4], lrow[4];
#pragma unroll
    for (int i = 0; i < 4; i++) {
        mrow[i] = -1e30f; lrow[i] = 0.f;
#pragma unroll
        for (int j = 0; j < 4; j++) acc[i][j] = 0.f;
    }

    __syncthreads();

    for (int kt = 0; kt < S_ / QT; kt++) {
        // Load K, V tiles
        const float* Kt = Kp + (size_t)kt * QT * D_;
        const float* Vt = Vp + (size_t)kt * QT * D_;
        for (int e = tid; e < QT * D_ / 4; e += 256) {
            int r = e >> 4, c = e & 15;
            *reinterpret_cast<float4*>(&Ks[r * STRIDE + c * 4]) =
                reinterpret_cast<const float4*>(Kt)[e];
            *reinterpret_cast<float4*>(&Vs[r * STRIDE + c * 4]) =
                reinterpret_cast<const float4*>(Vt)[e];
        }
        __syncthreads();

        // ---- scores: s[i][j] = Qs[ty+16i] . Ks[tx+16j] (already scaled) ----
        float s[4][4];
#pragma unroll
        for (int i = 0; i < 4; i++)
#pragma unroll
            for (int j = 0; j < 4; j++) s[i][j] = 0.f;

        const float4* Qs4 = reinterpret_cast<const float4*>(Qs);
        const float4* Ks4 = reinterpret_cast<const float4*>(Ks);
#pragma unroll
        for (int c = 0; c < 16; c++) {
            float4 q4[4], k4[4];
#pragma unroll
            for (int i = 0; i < 4; i++) q4[i] = Qs4[(ty + 16 * i) * ST4 + c];
#pragma unroll
            for (int j = 0; j < 4; j++) k4[j] = Ks4[(tx + 16 * j) * ST4 + c];
#pragma unroll
            for (int i = 0; i < 4; i++)
#pragma unroll
                for (int j = 0; j < 4; j++) {
                    s[i][j] += q4[i].x * k4[j].x;
                    s[i][j] += q4[i].y * k4[j].y;
                    s[i][j] += q4[i].z * k4[j].z;
                    s[i][j] += q4[i].w * k4[j].w;
                }
        }

        // ---- online softmax + dropout, per row ----
#pragma unroll
        for (int i = 0; i < 4; i++) {
            float rmax = fmaxf(fmaxf(s[i][0], s[i][1]), fmaxf(s[i][2], s[i][3]));
#pragma unroll
            for (int o = 1; o < 16; o <<= 1)
                rmax = fmaxf(rmax, __shfl_xor_sync(0xffffffffu, rmax, o));
            float mnew = fmaxf(mrow[i], rmax);
            float corr = __expf(mrow[i] - mnew);
            mrow[i] = mnew;

            float psum = 0.f;
#pragma unroll
            for (int j = 0; j < 4; j++) {
                s[i][j] = __expf(s[i][j] - mnew);
                psum += s[i][j];
            }
#pragma unroll
            for (int o = 1; o < 16; o <<= 1)
                psum += __shfl_xor_sync(0xffffffffu, psum, o);

            lrow[i] = lrow[i] * corr + psum;
#pragma unroll
            for (int j = 0; j < 4; j++) acc[i][j] *= corr;

            // dropout: bit index = ((bh*S + qrow)*S + kt*64 + (tx+16j))
            size_t bitbase = ((size_t)bh * S_ + (size_t)(qb + ty + 16 * i)) * S_
                             + (size_t)kt * QT;
            const uint32_t* mp = g_mask + (bitbase >> 5);
            uint32_t lo = mp[0], hi = mp[1];
            if (!((lo >> tx)        & 1u)) s[i][0] = 0.f;
            if (!((lo >> (tx + 16)) & 1u)) s[i][1] = 0.f;
            if (!((hi >> tx)        & 1u)) s[i][2] = 0.f;
            if (!((hi >> (tx + 16)) & 1u)) s[i][3] = 0.f;

#pragma unroll
            for (int j = 0; j < 4; j++)
                Ps[(ty + 16 * i) * STRIDE + tx + 16 * j] = s[i][j];
        }
        __syncthreads();

        // ---- PV: acc[i][j] += sum_k Ps[row_i][k] * Vs[k][col_j] ----
#pragma unroll 4
        for (int k = 0; k < QT; k++) {
            float b0 = Vs[k * STRIDE + tx];
            float b1 = Vs[k * STRIDE + tx + 16];
            float b2 = Vs[k * STRIDE + tx + 32];
            float b3 = Vs[k * STRIDE + tx + 48];
#pragma unroll
            for (int i = 0; i < 4; i++) {
                float a = Ps[(ty + 16 * i) * STRIDE + k];
                acc[i][0] += a * b0;
                acc[i][1] += a * b1;
                acc[i][2] += a * b2;
                acc[i][3] += a * b3;
            }
        }
        __syncthreads();
    }

    // ---- epilogue: O = acc / (l * 0.9) ----
    float* Op = O + ((size_t)bh * S_ + qb) * D_;
#pragma unroll
    for (int i = 0; i < 4; i++) {
        float inv = 1.0f / (lrow[i] * 0.9f);
#pragma unroll
        for (int j = 0; j < 4; j++)
            Op[(ty + 16 * i) * D_ + tx + 16 * j] = acc[i][j] * inv;
    }
}

// ---------------------------------------------------------------------------
extern "C" void kernel_launch(void* const* d_in, const int* in_sizes, int n_in,
                              void* d_out, int out_size) {
    (void)in_sizes; (void)n_in; (void)out_size;
    const float*    Q  = (const float*)d_in[0];
    const float*    K  = (const float*)d_in[1];
    const float*    V  = (const float*)d_in[2];
    const uint32_t* SC = (const uint32_t*)d_in[3];
    float*          O  = (float*)d_out;

#if JAX_PARTITIONABLE
    mask_kernel<<<NWORDS / 256, 256>>>();
#else
    mask_kernel<<<(NWORDS / 2) / 256, 256>>>();
#endif

    static const size_t smem = 4 * QT * STRIDE * sizeof(float);  // 69632 B
    cudaFuncSetAttribute(attn_kernel,
                         cudaFuncAttributeMaxDynamicSharedMemorySize, (int)smem);
    dim3 grid(S_ / QT, B_ * H_);
    attn_kernel<<<grid, 256, smem>>>(Q, K, V, SC, O);
}

// round 3
// speedup vs baseline: 1.0006x; 1.0006x over previous
#include <cuda_runtime.h>
#include <cstdint>

// Problem constants
#define B_ 4
#define H_ 16
#define S_ 1024
#define D_ 64

// 1 => JAX jax_threefry_partitionable=True (default since JAX 0.4.36):
//      bits[i] = x0^x1 of threefry((0,42),(0,i))
// 0 => legacy path: counters split in halves, bits[i]=out0 (i<n/2) / out1
#define JAX_PARTITIONABLE 1

#define NTOT   ((size_t)B_ * H_ * S_ * S_)   // 2^26 mask bits
#define NWORDS (NTOT / 32)                   // 2^21 uint32 words

__device__ uint32_t g_mask[NWORDS];          // 8 MB scratch (static, allowed)

// ---------------------------------------------------------------------------
// Threefry-2x32 (20 rounds), matches jax/_src/prng.py
// ---------------------------------------------------------------------------
__device__ __forceinline__ void threefry2x32(uint32_t k0, uint32_t k1,
                                             uint32_t& x0, uint32_t& x1) {
    uint32_t ks2 = 0x1BD11BDAu ^ k0 ^ k1;
    x0 += k0; x1 += k1;
#define TF_RND(r) { x0 += x1; x1 = __funnelshift_l(x1, x1, (r)); x1 ^= x0; }
    TF_RND(13) TF_RND(15) TF_RND(26) TF_RND(6)
    x0 += k1;  x1 += ks2 + 1u;
    TF_RND(17) TF_RND(29) TF_RND(16) TF_RND(24)
    x0 += ks2; x1 += k0 + 2u;
    TF_RND(13) TF_RND(15) TF_RND(26) TF_RND(6)
    x0 += k0;  x1 += k1 + 3u;
    TF_RND(17) TF_RND(29) TF_RND(16) TF_RND(24)
    x0 += k1;  x1 += ks2 + 4u;
    TF_RND(13) TF_RND(15) TF_RND(26) TF_RND(6)
    x0 += ks2; x1 += k0 + 5u;
#undef TF_RND
}

// keep  <=>  uniform(bits) < 0.9f  <=>  (bits>>9) < 0x733333  <=>  bits < 0xE6666600
#define KEEP_THRESH 0xE6666600u

// ---------------------------------------------------------------------------
// Mask precompute: one 32-bit mask word per thread
// ---------------------------------------------------------------------------
__global__ void __launch_bounds__(256) mask_kernel() {
    uint32_t t = blockIdx.x * 256u + threadIdx.x;       // [0, NWORDS) or [0, NWORDS/2)
#if JAX_PARTITIONABLE
    uint32_t base = t * 32u;
    uint32_t w = 0u;
#pragma unroll 4
    for (int b = 0; b < 32; b++) {
        uint32_t x0 = 0u, x1 = base + (uint32_t)b;      // (hi, lo) of 64-bit iota
        threefry2x32(0u, 42u, x0, x1);
        uint32_t bits = x0 ^ x1;
        w |= (bits < KEEP_THRESH ? 1u : 0u) << b;
    }
    g_mask[t] = w;
#else
    // legacy: counters [0..n) split into halves; (out0,out1)=threefry(key, i, i+n/2)
    const uint32_t HALF = (uint32_t)(NTOT / 2);
    uint32_t base = t * 32u;                            // t in [0, NWORDS/2)
    uint32_t w0 = 0u, w1 = 0u;
#pragma unroll 4
    for (int b = 0; b < 32; b++) {
        uint32_t x0 = base + (uint32_t)b;
        uint32_t x1 = x0 + HALF;
        threefry2x32(0u, 42u, x0, x1);
        w0 |= (x0 < KEEP_THRESH ? 1u : 0u) << b;
        w1 |= (x1 < KEEP_THRESH ? 1u : 0u) << b;
    }
    g_mask[t] = w0;
    g_mask[t + NWORDS / 2] = w1;
#endif
}

// ---------------------------------------------------------------------------
// Flash attention, fp32, 64x64 tiles, 256 threads, 4x4 strided micro-tiles
// ---------------------------------------------------------------------------
#define QT 64
#define STRIDE 68        // padded float stride (conflict mitigation + 16B align)
#define ST4 17           // STRIDE/4

__global__ void __launch_bounds__(256, 2)
attn_kernel(const float* __restrict__ Q, const float* __restrict__ K,
            const float* __restrict__ V, const uint32_t* __restrict__ scale_ptr,
            float* __restrict__ O) {
    extern __shared__ float sm[];
    float* Qs = sm;                      // QT x STRIDE (pre-scaled by scale_factor)
    float* Ks = sm + QT * STRIDE;
    float* Vs = sm + 2 * QT * STRIDE;
    float* Ps = sm + 3 * QT * STRIDE;

    const int tid = threadIdx.x;
    const int bh  = blockIdx.y;          // b*H + h
    const int qb  = blockIdx.x * QT;

    // scale_factor may arrive as int32(8) or float32(8.0); decode either
    uint32_t sw = *scale_ptr;
    float scale = (sw & 0x7f800000u) ? __uint_as_float(sw) : (float)(int)sw;

    const float* Qp = Q + ((size_t)bh * S_ + qb) * D_;
    const float* Kp = K + (size_t)bh * S_ * D_;
    const float* Vp = V + (size_t)bh * S_ * D_;

    // Load Q tile (scaled)
    for (int e = tid; e < QT * D_ / 4; e += 256) {
        int r = e >> 4, c = e & 15;
        float4 v = reinterpret_cast<const float4*>(Qp)[e];
        v.x *= scale; v.y *= scale; v.z *= scale; v.w *= scale;
        *reinterpret_cast<float4*>(&Qs[r * STRIDE + c * 4]) = v;
    }

    const int ty = tid >> 4;             // 0..15 (row group)
    const int tx = tid & 15;             // 0..15 (col group)

    float acc[4][4];
    float mrow[4], lrow[4];
#pragma unroll
    for (int i = 0; i < 4; i++) {
        mrow[i] = -1e30f; lrow[i] = 0.f;
#pragma unroll
        for (int j = 0; j < 4; j++) acc[i][j] = 0.f;
    }

    __syncthreads();

    for (int kt = 0; kt < S_ / QT; kt++) {
        // Load K, V tiles
        const float* Kt = Kp + (size_t)kt * QT * D_;
        const float* Vt = Vp + (size_t)kt * QT * D_;
        for (int e = tid; e < QT * D_ / 4; e += 256) {
            int r = e >> 4, c = e & 15;
            *reinterpret_cast<float4*>(&Ks[r * STRIDE + c * 4]) =
                reinterpret_cast<const float4*>(Kt)[e];
            *reinterpret_cast<float4*>(&Vs[r * STRIDE + c * 4]) =
                reinterpret_cast<const float4*>(Vt)[e];
        }
        __syncthreads();

        // ---- scores: s[i][j] = Qs[ty+16i] . Ks[tx+16j] (already scaled) ----
        float s[4][4];
#pragma unroll
        for (int i = 0; i < 4; i++)
#pragma unroll
            for (int j = 0; j < 4; j++) s[i][j] = 0.f;

        const float4* Qs4 = reinterpret_cast<const float4*>(Qs);
        const float4* Ks4 = reinterpret_cast<const float4*>(Ks);
#pragma unroll
        for (int c = 0; c < 16; c++) {
            float4 q4[4], k4[4];
#pragma unroll
            for (int i = 0; i < 4; i++) q4[i] = Qs4[(ty + 16 * i) * ST4 + c];
#pragma unroll
            for (int j = 0; j < 4; j++) k4[j] = Ks4[(tx + 16 * j) * ST4 + c];
#pragma unroll
            for (int i = 0; i < 4; i++)
#pragma unroll
                for (int j = 0; j < 4; j++) {
                    s[i][j] += q4[i].x * k4[j].x;
                    s[i][j] += q4[i].y * k4[j].y;
                    s[i][j] += q4[i].z * k4[j].z;
                    s[i][j] += q4[i].w * k4[j].w;
                }
        }

        // ---- online softmax + dropout, per row ----
#pragma unroll
        for (int i = 0; i < 4; i++) {
            float rmax = fmaxf(fmaxf(s[i][0], s[i][1]), fmaxf(s[i][2], s[i][3]));
#pragma unroll
            for (int o = 1; o < 16; o <<= 1)
                rmax = fmaxf(rmax, __shfl_xor_sync(0xffffffffu, rmax, o));
            float mnew = fmaxf(mrow[i], rmax);
            float corr = __expf(mrow[i] - mnew);
            mrow[i] = mnew;

            float psum = 0.f;
#pragma unroll
            for (int j = 0; j < 4; j++) {
                s[i][j] = __expf(s[i][j] - mnew);
                psum += s[i][j];
            }
#pragma unroll
            for (int o = 1; o < 16; o <<= 1)
                psum += __shfl_xor_sync(0xffffffffu, psum, o);

            lrow[i] = lrow[i] * corr + psum;
#pragma unroll
            for (int j = 0; j < 4; j++) acc[i][j] *= corr;

            // dropout: bit index = ((bh*S + qrow)*S + kt*64 + (tx+16j))
            size_t bitbase = ((size_t)bh * S_ + (size_t)(qb + ty + 16 * i)) * S_
                             + (size_t)kt * QT;
            const uint32_t* mp = g_mask + (bitbase >> 5);
            uint32_t lo = mp[0], hi = mp[1];
            if (!((lo >> tx)        & 1u)) s[i][0] = 0.f;
            if (!((lo >> (tx + 16)) & 1u)) s[i][1] = 0.f;
            if (!((hi >> tx)        & 1u)) s[i][2] = 0.f;
            if (!((hi >> (tx + 16)) & 1u)) s[i][3] = 0.f;

#pragma unroll
            for (int j = 0; j < 4; j++)
                Ps[(ty + 16 * i) * STRIDE + tx + 16 * j] = s[i][j];
        }
        __syncthreads();

        // ---- PV: acc[i][j] += sum_k Ps[row_i][k] * Vs[k][col_j] ----
#pragma unroll 4
        for (int k = 0; k < QT; k++) {
            float b0 = Vs[k * STRIDE + tx];
            float b1 = Vs[k * STRIDE + tx + 16];
            float b2 = Vs[k * STRIDE + tx + 32];
            float b3 = Vs[k * STRIDE + tx + 48];
#pragma unroll
            for (int i = 0; i < 4; i++) {
                float a = Ps[(ty + 16 * i) * STRIDE + k];
                acc[i][0] += a * b0;
                acc[i][1] += a * b1;
                acc[i][2] += a * b2;
                acc[i][3] += a * b3;
            }
        }
        __syncthreads();
    }

    // ---- epilogue: O = acc / (l * 0.9) ----
    float* Op = O + ((size_t)bh * S_ + qb) * D_;
#pragma unroll
    for (int i = 0; i < 4; i++) {
        float inv = 1.0f / (lrow[i] * 0.9f);
#pragma unroll
        for (int j = 0; j < 4; j++)
            Op[(ty + 16 * i) * D_ + tx + 16 * j] = acc[i][j] * inv;
    }
}

// ---------------------------------------------------------------------------
extern "C" void kernel_launch(void* const* d_in, const int* in_sizes, int n_in,
                              void* d_out, int out_size) {
    (void)in_sizes; (void)n_in; (void)out_size;
    const float*    Q  = (const float*)d_in[0];
    const float*    K  = (const float*)d_in[1];
    const float*    V  = (const float*)d_in[2];
    const uint32_t* SC = (const uint32_t*)d_in[3];
    float*          O  = (float*)d_out;

#if JAX_PARTITIONABLE
    mask_kernel<<<NWORDS / 256, 256>>>();
#else
    mask_kernel<<<(NWORDS / 2) / 256, 256>>>();
#endif

    static const size_t smem = 4 * QT * STRIDE * sizeof(float);  // 69632 B
    cudaFuncSetAttribute(attn_kernel,
                         cudaFuncAttributeMaxDynamicSharedMemorySize, (int)smem);
    dim3 grid(S_ / QT, B_ * H_);
    attn_kernel<<<grid, 256, smem>>>(Q, K, V, SC, O);
}

// round 5
// speedup vs baseline: 1.1937x; 1.1930x over previous
#include <cuda_runtime.h>
#include <cstdint>

#define B_ 4
#define H_ 16
#define S_ 1024
#define D_ 64
#define NTOT   ((size_t)B_ * H_ * S_ * S_)
#define NWORDS (NTOT / 32)

__device__ uint32_t g_mask[NWORDS];   // 8 MB bitmask scratch

// ---------------------------------------------------------------------------
// Threefry-2x32, bit-exact vs JAX partitionable path (verified: rel_err 6e-8)
// ---------------------------------------------------------------------------
__device__ __forceinline__ void threefry2x32(uint32_t k0, uint32_t k1,
                                             uint32_t& x0, uint32_t& x1) {
    uint32_t ks2 = 0x1BD11BDAu ^ k0 ^ k1;
    x0 += k0; x1 += k1;
#define TF_RND(r) { x0 += x1; x1 = __funnelshift_l(x1, x1, (r)); x1 ^= x0; }
    TF_RND(13) TF_RND(15) TF_RND(26) TF_RND(6)
    x0 += k1;  x1 += ks2 + 1u;
    TF_RND(17) TF_RND(29) TF_RND(16) TF_RND(24)
    x0 += ks2; x1 += k0 + 2u;
    TF_RND(13) TF_RND(15) TF_RND(26) TF_RND(6)
    x0 += k0;  x1 += k1 + 3u;
    TF_RND(17) TF_RND(29) TF_RND(16) TF_RND(24)
    x0 += k1;  x1 += ks2 + 4u;
    TF_RND(13) TF_RND(15) TF_RND(26) TF_RND(6)
    x0 += ks2; x1 += k0 + 5u;
#undef TF_RND
}

#define KEEP_THRESH 0xE6666600u

__global__ void __launch_bounds__(256) mask_kernel() {
    uint32_t t = blockIdx.x * 256u + threadIdx.x;
    uint32_t base = t * 32u;
    uint32_t w = 0u;
#pragma unroll 4
    for (int b = 0; b < 32; b++) {
        uint32_t x0 = 0u, x1 = base + (uint32_t)b;
        threefry2x32(0u, 42u, x0, x1);
        w |= (((x0 ^ x1) < KEEP_THRESH) ? 1u : 0u) << b;
    }
    g_mask[t] = w;
}

// ---------------------------------------------------------------------------
// helpers
// ---------------------------------------------------------------------------
__device__ __forceinline__ uint32_t f2tf32(float x) {
    uint32_t r;
    asm("cvt.rna.tf32.f32 %0, %1;" : "=r"(r) : "f"(x));
    return r;
}

// d += A(tf32) * B(tf32), m16n8k8
__device__ __forceinline__ void mma8(float d[4], const uint32_t a[4],
                                     uint32_t b0, uint32_t b1) {
    asm volatile(
        "mma.sync.aligned.m16n8k8.row.col.f32.tf32.tf32.f32 "
        "{%0,%1,%2,%3}, {%4,%5,%6,%7}, {%8,%9}, {%0,%1,%2,%3};"
        : "+f"(d[0]), "+f"(d[1]), "+f"(d[2]), "+f"(d[3])
        : "r"(a[0]), "r"(a[1]), "r"(a[2]), "r"(a[3]), "r"(b0), "r"(b1));
}

#define PAD 68   // float stride: conflict-free lane->bank mapping

// smem float offsets
#define O_QH 0
#define O_QL (128 * PAD)
#define O_KH (2 * 128 * PAD)
#define O_KL (2 * 128 * PAD + 64 * PAD)
#define O_VS (2 * 128 * PAD + 2 * 64 * PAD)
#define O_PH (2 * 128 * PAD + 3 * 64 * PAD)
#define O_PL (3 * 128 * PAD + 3 * 64 * PAD)
#define SMEM_FLOATS (4 * 128 * PAD + 3 * 64 * PAD)   // 47872 floats = 191488 B

// ---------------------------------------------------------------------------
__global__ void __launch_bounds__(128, 1)
attn_kernel(const float* __restrict__ Q, const float* __restrict__ K,
            const float* __restrict__ V, const uint32_t* __restrict__ scale_ptr,
            float* __restrict__ O) {
    extern __shared__ float sm[];
    float* Qh = sm + O_QH;
    float* Ql = sm + O_QL;
    float* Kh = sm + O_KH;
    float* Kl = sm + O_KL;
    float* Vs = sm + O_VS;
    float* Ph = sm + O_PH;
    float* Pl = sm + O_PL;

    const int tid  = threadIdx.x;
    const int warp = tid >> 5;
    const int lane = tid & 31;
    const int gid  = lane >> 2;          // 0..7
    const int tig  = lane & 3;           // 0..3
    const int bh   = blockIdx.y;
    const int qb   = blockIdx.x << 7;

    uint32_t sw = *scale_ptr;
    float scale = (sw & 0x7f800000u) ? __uint_as_float(sw) : (float)(int)sw;

    // ---- Q load: thread owns row tid; pre-scale, split hi/lo tf32 ----
    {
        const float4* Qp = reinterpret_cast<const float4*>(
            Q + ((size_t)bh * S_ + qb + tid) * D_);
        float* qh = Qh + tid * PAD;
        float* ql = Ql + tid * PAD;
#pragma unroll
        for (int i = 0; i < 16; i++) {
            float4 v = Qp[i];
            float f[4] = {v.x, v.y, v.z, v.w};
#pragma unroll
            for (int j = 0; j < 4; j++) {
                float x = f[j] * scale;
                uint32_t h = f2tf32(x);
                qh[i * 4 + j] = __uint_as_float(h);
                ql[i * 4 + j] = __uint_as_float(f2tf32(x - __uint_as_float(h)));
            }
        }
    }

    float m_[4], l_[4];
    float o[2][8][4];
#pragma unroll
    for (int i = 0; i < 4; i++) { m_[i] = -1e30f; l_[i] = 0.f; }
#pragma unroll
    for (int mf = 0; mf < 2; mf++)
#pragma unroll
        for (int n = 0; n < 8; n++)
#pragma unroll
            for (int c = 0; c < 4; c++) o[mf][n][c] = 0.f;

    const int row_base = warp * 32;      // warp's 32 rows within the 128-row tile

    for (int t = 0; t < 16; t++) {
        __syncthreads();                 // everyone done reading prev K/V
        // ---- K,V tile load: thread owns half-row; split K hi/lo, round V ----
        {
            int r = tid >> 1, half = (tid & 1) * 32;
            const float4* Kt = reinterpret_cast<const float4*>(
                K + ((size_t)bh * S_ + t * 64 + r) * D_ + half);
            const float4* Vt = reinterpret_cast<const float4*>(
                V + ((size_t)bh * S_ + t * 64 + r) * D_ + half);
            float* kh = Kh + r * PAD + half;
            float* kl = Kl + r * PAD + half;
            float* vs = Vs + r * PAD + half;
#pragma unroll
            for (int i = 0; i < 8; i++) {
                float4 kv = Kt[i];
                float kf[4] = {kv.x, kv.y, kv.z, kv.w};
#pragma unroll
                for (int j = 0; j < 4; j++) {
                    uint32_t h = f2tf32(kf[j]);
                    kh[i * 4 + j] = __uint_as_float(h);
                    kl[i * 4 + j] = __uint_as_float(f2tf32(kf[j] - __uint_as_float(h)));
                }
                float4 vv = Vt[i];
                float vf[4] = {vv.x, vv.y, vv.z, vv.w};
#pragma unroll
                for (int j = 0; j < 4; j++)
                    vs[i * 4 + j] = __uint_as_float(f2tf32(vf[j]));
            }
        }
        __syncthreads();

        // ---- QK: 3xTF32 (qh*kh + ql*kh + qh*kl) ----
        float s[2][8][4];
#pragma unroll
        for (int mf = 0; mf < 2; mf++)
#pragma unroll
            for (int n = 0; n < 8; n++)
#pragma unroll
                for (int c = 0; c < 4; c++) s[mf][n][c] = 0.f;

#pragma unroll
        for (int ks = 0; ks < 8; ks++) {
            uint32_t aqh[2][4], aql[2][4];
#pragma unroll
            for (int mf = 0; mf < 2; mf++) {
                int r0 = row_base + mf * 16 + gid;
                int c0 = ks * 8 + tig;
                aqh[mf][0] = __float_as_uint(Qh[r0 * PAD + c0]);
                aqh[mf][1] = __float_as_uint(Qh[(r0 + 8) * PAD + c0]);
                aqh[mf][2] = __float_as_uint(Qh[r0 * PAD + c0 + 4]);
                aqh[mf][3] = __float_as_uint(Qh[(r0 + 8) * PAD + c0 + 4]);
                aql[mf][0] = __float_as_uint(Ql[r0 * PAD + c0]);
                aql[mf][1] = __float_as_uint(Ql[(r0 + 8) * PAD + c0]);
                aql[mf][2] = __float_as_uint(Ql[r0 * PAD + c0 + 4]);
                aql[mf][3] = __float_as_uint(Ql[(r0 + 8) * PAD + c0 + 4]);
            }
#pragma unroll
            for (int n = 0; n < 8; n++) {
                int kr = n * 8 + gid;
                int c0 = ks * 8 + tig;
                uint32_t bh0 = __float_as_uint(Kh[kr * PAD + c0]);
                uint32_t bh1 = __float_as_uint(Kh[kr * PAD + c0 + 4]);
                uint32_t bl0 = __float_as_uint(Kl[kr * PAD + c0]);
                uint32_t bl1 = __float_as_uint(Kl[kr * PAD + c0 + 4]);
#pragma unroll
                for (int mf = 0; mf < 2; mf++) {
                    mma8(s[mf][n], aqh[mf], bh0, bh1);
                    mma8(s[mf][n], aql[mf], bh0, bh1);
                    mma8(s[mf][n], aqh[mf], bl0, bl1);
                }
            }
        }

        // ---- online softmax (rows live on lane quads) ----
#pragma unroll
        for (int mf = 0; mf < 2; mf++) {
#pragma unroll
            for (int h = 0; h < 2; h++) {
                int idx = mf * 2 + h;
                float mx = -1e30f;
#pragma unroll
                for (int n = 0; n < 8; n++)
                    mx = fmaxf(mx, fmaxf(s[mf][n][2 * h], s[mf][n][2 * h + 1]));
                mx = fmaxf(mx, __shfl_xor_sync(0xffffffffu, mx, 1));
                mx = fmaxf(mx, __shfl_xor_sync(0xffffffffu, mx, 2));
                float mnew = fmaxf(m_[idx], mx);
                float corr = __expf(m_[idx] - mnew);
                m_[idx] = mnew;
                float sum = 0.f;
#pragma unroll
                for (int n = 0; n < 8; n++) {
                    float e0 = __expf(s[mf][n][2 * h] - mnew);
                    float e1 = __expf(s[mf][n][2 * h + 1] - mnew);
                    s[mf][n][2 * h] = e0;
                    s[mf][n][2 * h + 1] = e1;
                    sum += e0 + e1;
                }
                sum += __shfl_xor_sync(0xffffffffu, sum, 1);
                sum += __shfl_xor_sync(0xffffffffu, sum, 2);
                l_[idx] = l_[idx] * corr + sum;
#pragma unroll
                for (int n = 0; n < 8; n++) {
                    o[mf][n][2 * h] *= corr;
                    o[mf][n][2 * h + 1] *= corr;
                }
            }
        }

        // ---- dropout + P (hi/lo) to smem ----
#pragma unroll
        for (int mf = 0; mf < 2; mf++) {
#pragma unroll
            for (int h = 0; h < 2; h++) {
                int rloc = row_base + mf * 16 + gid + h * 8;
                size_t rg = (size_t)(bh * S_ + qb + rloc);
                uint2 w = *reinterpret_cast<const uint2*>(g_mask + (rg << 5) + t * 2);
#pragma unroll
                for (int n = 0; n < 8; n++) {
                    uint32_t word = (n < 4) ? w.x : w.y;
                    int bit0 = (n & 3) * 8 + 2 * tig;
                    float p0 = ((word >> bit0) & 1u) ? s[mf][n][2 * h] : 0.f;
                    float p1 = ((word >> (bit0 + 1)) & 1u) ? s[mf][n][2 * h + 1] : 0.f;
                    uint32_t h0 = f2tf32(p0), h1 = f2tf32(p1);
                    int off = rloc * PAD + n * 8 + 2 * tig;
                    Ph[off]     = __uint_as_float(h0);
                    Ph[off + 1] = __uint_as_float(h1);
                    Pl[off]     = __uint_as_float(f2tf32(p0 - __uint_as_float(h0)));
                    Pl[off + 1] = __uint_as_float(f2tf32(p1 - __uint_as_float(h1)));
                }
            }
        }
        __syncwarp();   // P is warp-private: order sts before lds within warp

        // ---- PV: 2-term (ph*v + pl*v), accumulate into O regs ----
#pragma unroll
        for (int ks = 0; ks < 8; ks++) {
            uint32_t aph[2][4], apl[2][4];
#pragma unroll
            for (int mf = 0; mf < 2; mf++) {
                int r0 = row_base + mf * 16 + gid;
                int c0 = ks * 8 + tig;
                aph[mf][0] = __float_as_uint(Ph[r0 * PAD + c0]);
                aph[mf][1] = __float_as_uint(Ph[(r0 + 8) * PAD + c0]);
                aph[mf][2] = __float_as_uint(Ph[r0 * PAD + c0 + 4]);
                aph[mf][3] = __float_as_uint(Ph[(r0 + 8) * PAD + c0 + 4]);
                apl[mf][0] = __float_as_uint(Pl[r0 * PAD + c0]);
                apl[mf][1] = __float_as_uint(Pl[(r0 + 8) * PAD + c0]);
                apl[mf][2] = __float_as_uint(Pl[r0 * PAD + c0 + 4]);
                apl[mf][3] = __float_as_uint(Pl[(r0 + 8) * PAD + c0 + 4]);
            }
#pragma unroll
            for (int n = 0; n < 8; n++) {
                uint32_t b0 = __float_as_uint(Vs[(ks * 8 + tig) * PAD + n * 8 + gid]);
                uint32_t b1 = __float_as_uint(Vs[(ks * 8 + tig + 4) * PAD + n * 8 + gid]);
#pragma unroll
                for (int mf = 0; mf < 2; mf++) {
                    mma8(o[mf][n], aph[mf], b0, b1);
                    mma8(o[mf][n], apl[mf], b0, b1);
                }
            }
        }
    }

    // ---- epilogue: O / (0.9 * l), write global ----
#pragma unroll
    for (int mf = 0; mf < 2; mf++) {
#pragma unroll
        for (int h = 0; h < 2; h++) {
            float inv = 1.f / (0.9f * l_[mf * 2 + h]);
            int row = qb + row_base + mf * 16 + gid + h * 8;
            float* Op = O + ((size_t)bh * S_ + row) * D_;
#pragma unroll
            for (int n = 0; n < 8; n++) {
                float2 v;
                v.x = o[mf][n][2 * h] * inv;
                v.y = o[mf][n][2 * h + 1] * inv;
                *reinterpret_cast<float2*>(Op + n * 8 + 2 * tig) = v;
            }
        }
    }
}

// ---------------------------------------------------------------------------
extern "C" void kernel_launch(void* const* d_in, const int* in_sizes, int n_in,
                              void* d_out, int out_size) {
    (void)in_sizes; (void)n_in; (void)out_size;
    const float*    Q  = (const float*)d_in[0];
    const float*    K  = (const float*)d_in[1];
    const float*    V  = (const float*)d_in[2];
    const uint32_t* SC = (const uint32_t*)d_in[3];
    float*          O  = (float*)d_out;

    mask_kernel<<<NWORDS / 256, 256>>>();

    static const int smem = SMEM_FLOATS * (int)sizeof(float);   // 191488
    cudaFuncSetAttribute(attn_kernel,
                         cudaFuncAttributeMaxDynamicSharedMemorySize, smem);
    dim3 grid(S_ / 128, B_ * H_);
    attn_kernel<<<grid, 128, smem>>>(Q, K, V, SC, O);
}

// round 6
// speedup vs baseline: 1.2940x; 1.0840x over previous
#include <cuda_runtime.h>
#include <cstdint>

#define B_ 4
#define H_ 16
#define S_ 1024
#define D_ 64
#define NTOT   ((size_t)B_ * H_ * S_ * S_)
#define NWORDS (NTOT / 32)

__device__ uint32_t g_mask[NWORDS];   // 8 MB bitmask scratch

// ---------------------------------------------------------------------------
// Threefry-2x32, bit-exact vs JAX partitionable path (verified: rel_err 6e-8)
// ---------------------------------------------------------------------------
__device__ __forceinline__ void threefry2x32(uint32_t k0, uint32_t k1,
                                             uint32_t& x0, uint32_t& x1) {
    uint32_t ks2 = 0x1BD11BDAu ^ k0 ^ k1;
    x0 += k0; x1 += k1;
#define TF_RND(r) { x0 += x1; x1 = __funnelshift_l(x1, x1, (r)); x1 ^= x0; }
    TF_RND(13) TF_RND(15) TF_RND(26) TF_RND(6)
    x0 += k1;  x1 += ks2 + 1u;
    TF_RND(17) TF_RND(29) TF_RND(16) TF_RND(24)
    x0 += ks2; x1 += k0 + 2u;
    TF_RND(13) TF_RND(15) TF_RND(26) TF_RND(6)
    x0 += k0;  x1 += k1 + 3u;
    TF_RND(17) TF_RND(29) TF_RND(16) TF_RND(24)
    x0 += k1;  x1 += ks2 + 4u;
    TF_RND(13) TF_RND(15) TF_RND(26) TF_RND(6)
    x0 += ks2; x1 += k0 + 5u;
#undef TF_RND
}

#define KEEP_THRESH 0xE6666600u

__global__ void __launch_bounds__(256) mask_kernel() {
    uint32_t t = blockIdx.x * 256u + threadIdx.x;
    uint32_t base = t * 32u;
    uint32_t w = 0u;
#pragma unroll 4
    for (int b = 0; b < 32; b++) {
        uint32_t x0 = 0u, x1 = base + (uint32_t)b;
        threefry2x32(0u, 42u, x0, x1);
        w |= (((x0 ^ x1) < KEEP_THRESH) ? 1u : 0u) << b;
    }
    g_mask[t] = w;
}

// ---------------------------------------------------------------------------
// helpers
// ---------------------------------------------------------------------------
__device__ __forceinline__ uint32_t f2tf32(float x) {
    uint32_t r;
    asm("cvt.rna.tf32.f32 %0, %1;" : "=r"(r) : "f"(x));
    return r;
}

// d += A(tf32) * B(tf32), m16n8k8
__device__ __forceinline__ void mma8(float d[4], const uint32_t a[4],
                                     uint32_t b0, uint32_t b1) {
    asm volatile(
        "mma.sync.aligned.m16n8k8.row.col.f32.tf32.tf32.f32 "
        "{%0,%1,%2,%3}, {%4,%5,%6,%7}, {%8,%9}, {%0,%1,%2,%3};"
        : "+f"(d[0]), "+f"(d[1]), "+f"(d[2]), "+f"(d[3])
        : "r"(a[0]), "r"(a[1]), "r"(a[2]), "r"(a[3]), "r"(b0), "r"(b1));
}

#define PAD 68   // float stride: conflict-free lane->bank mapping

// smem float offsets.  P region ALIASES the Q staging region (Q fragments are
// hoisted into registers before the mainloop touches P).
#define O_PH 0
#define O_PL (128 * PAD)
#define O_KH (2 * 128 * PAD)
#define O_KL (2 * 128 * PAD + 64 * PAD)
#define O_VS (2 * 128 * PAD + 2 * 64 * PAD)
#define SMEM_FLOATS (2 * 128 * PAD + 3 * 64 * PAD)   // 30464 floats = 121856 B

// ---------------------------------------------------------------------------
__global__ void __launch_bounds__(256, 1)
attn_kernel(const float* __restrict__ Q, const float* __restrict__ K,
            const float* __restrict__ V, const uint32_t* __restrict__ scale_ptr,
            float* __restrict__ O) {
    extern __shared__ float sm[];
    float* Ph = sm + O_PH;       // also Q-hi staging during prologue
    float* Pl = sm + O_PL;       // also Q-lo staging during prologue
    float* Kh = sm + O_KH;
    float* Kl = sm + O_KL;
    float* Vs = sm + O_VS;

    const int tid  = threadIdx.x;
    const int warp = tid >> 5;           // 0..7, owns rows [16w, 16w+16)
    const int lane = tid & 31;
    const int gid  = lane >> 2;          // 0..7
    const int tig  = lane & 3;           // 0..3
    const int bh   = blockIdx.y;
    const int qb   = blockIdx.x << 7;

    uint32_t sw = *scale_ptr;
    float scale = (sw & 0x7f800000u) ? __uint_as_float(sw) : (float)(int)sw;

    // ---- Q prologue: stage scaled hi/lo rows, then hoist fragments to regs --
    {
        int r = tid >> 1, half = (tid & 1) * 32;
        const float4* Qp = reinterpret_cast<const float4*>(
            Q + ((size_t)bh * S_ + qb + r) * D_ + half);
        float* qh = Ph + r * PAD + half;
        float* ql = Pl + r * PAD + half;
#pragma unroll
        for (int i = 0; i < 8; i++) {
            float4 v = Qp[i];
            float f[4] = {v.x, v.y, v.z, v.w};
#pragma unroll
            for (int j = 0; j < 4; j++) {
                float x = f[j] * scale;
                uint32_t h = f2tf32(x);
                qh[i * 4 + j] = __uint_as_float(h);
                ql[i * 4 + j] = __uint_as_float(f2tf32(x - __uint_as_float(h)));
            }
        }
    }
    __syncthreads();

    uint32_t fqh[8][4], fql[8][4];       // tile-invariant Q fragments
    {
        const int r0 = warp * 16 + gid;
#pragma unroll
        for (int ks = 0; ks < 8; ks++) {
            int c0 = ks * 8 + tig;
            fqh[ks][0] = __float_as_uint(Ph[r0 * PAD + c0]);
            fqh[ks][1] = __float_as_uint(Ph[(r0 + 8) * PAD + c0]);
            fqh[ks][2] = __float_as_uint(Ph[r0 * PAD + c0 + 4]);
            fqh[ks][3] = __float_as_uint(Ph[(r0 + 8) * PAD + c0 + 4]);
            fql[ks][0] = __float_as_uint(Pl[r0 * PAD + c0]);
            fql[ks][1] = __float_as_uint(Pl[(r0 + 8) * PAD + c0]);
            fql[ks][2] = __float_as_uint(Pl[r0 * PAD + c0 + 4]);
            fql[ks][3] = __float_as_uint(Pl[(r0 + 8) * PAD + c0 + 4]);
        }
    }
    __syncthreads();                     // Q staging free -> P may reuse

    float m_[2], l_[2];
    float o[8][4];
    m_[0] = m_[1] = -1e30f;
    l_[0] = l_[1] = 0.f;
#pragma unroll
    for (int n = 0; n < 8; n++)
#pragma unroll
        for (int c = 0; c < 4; c++) o[n][c] = 0.f;

    const int row_base = warp * 16;

    for (int t = 0; t < 16; t++) {
        // ---- prefetch dropout words (hidden behind K/V load + QK) ----
        uint2 mw[2];
#pragma unroll
        for (int h = 0; h < 2; h++) {
            size_t rg = (size_t)(bh * S_ + qb + row_base + gid + 8 * h);
            mw[h] = *reinterpret_cast<const uint2*>(g_mask + (rg << 5) + t * 2);
        }

        __syncthreads();                 // PV(t-1) readers done with K/V/P
        // ---- K,V tile: thread owns quarter-row; split K hi/lo, round V ----
        {
            int r = tid >> 2, qtr = (tid & 3) * 16;
            const float4* Kt = reinterpret_cast<const float4*>(
                K + ((size_t)bh * S_ + t * 64 + r) * D_ + qtr);
            const float4* Vt = reinterpret_cast<const float4*>(
                V + ((size_t)bh * S_ + t * 64 + r) * D_ + qtr);
            float* kh = Kh + r * PAD + qtr;
            float* kl = Kl + r * PAD + qtr;
            float* vs = Vs + r * PAD + qtr;
#pragma unroll
            for (int i = 0; i < 4; i++) {
                float4 kv = Kt[i];
                float kf[4] = {kv.x, kv.y, kv.z, kv.w};
#pragma unroll
                for (int j = 0; j < 4; j++) {
                    uint32_t h = f2tf32(kf[j]);
                    kh[i * 4 + j] = __uint_as_float(h);
                    kl[i * 4 + j] = __uint_as_float(f2tf32(kf[j] - __uint_as_float(h)));
                }
                float4 vv = Vt[i];
                float vf[4] = {vv.x, vv.y, vv.z, vv.w};
#pragma unroll
                for (int j = 0; j < 4; j++)
                    vs[i * 4 + j] = __uint_as_float(f2tf32(vf[j]));
            }
        }
        __syncthreads();

        // ---- QK: 3xTF32 (qh*kh + ql*kh + qh*kl), Q from registers ----
        float s[8][4];
#pragma unroll
        for (int n = 0; n < 8; n++)
#pragma unroll
            for (int c = 0; c < 4; c++) s[n][c] = 0.f;

#pragma unroll
        for (int ks = 0; ks < 8; ks++) {
            int c0 = ks * 8 + tig;
#pragma unroll
            for (int n = 0; n < 8; n++) {
                int kr = n * 8 + gid;
                uint32_t bh0 = __float_as_uint(Kh[kr * PAD + c0]);
                uint32_t bh1 = __float_as_uint(Kh[kr * PAD + c0 + 4]);
                uint32_t bl0 = __float_as_uint(Kl[kr * PAD + c0]);
                uint32_t bl1 = __float_as_uint(Kl[kr * PAD + c0 + 4]);
                mma8(s[n], fqh[ks], bh0, bh1);
                mma8(s[n], fql[ks], bh0, bh1);
                mma8(s[n], fqh[ks], bl0, bl1);
            }
        }

        // ---- online softmax (row lives on a lane quad) ----
#pragma unroll
        for (int h = 0; h < 2; h++) {
            float mx = -1e30f;
#pragma unroll
            for (int n = 0; n < 8; n++)
                mx = fmaxf(mx, fmaxf(s[n][2 * h], s[n][2 * h + 1]));
            mx = fmaxf(mx, __shfl_xor_sync(0xffffffffu, mx, 1));
            mx = fmaxf(mx, __shfl_xor_sync(0xffffffffu, mx, 2));
            float mnew = fmaxf(m_[h], mx);
            float corr = __expf(m_[h] - mnew);
            m_[h] = mnew;
            float sum = 0.f;
#pragma unroll
            for (int n = 0; n < 8; n++) {
                float e0 = __expf(s[n][2 * h] - mnew);
                float e1 = __expf(s[n][2 * h + 1] - mnew);
                s[n][2 * h] = e0;
                s[n][2 * h + 1] = e1;
                sum += e0 + e1;
            }
            sum += __shfl_xor_sync(0xffffffffu, sum, 1);
            sum += __shfl_xor_sync(0xffffffffu, sum, 2);
            l_[h] = l_[h] * corr + sum;
#pragma unroll
            for (int n = 0; n < 8; n++) {
                o[n][2 * h] *= corr;
                o[n][2 * h + 1] *= corr;
            }
        }

        // ---- dropout + P (hi/lo) to smem ----
#pragma unroll
        for (int h = 0; h < 2; h++) {
            int rloc = row_base + gid + h * 8;
#pragma unroll
            for (int n = 0; n < 8; n++) {
                uint32_t word = (n < 4) ? mw[h].x : mw[h].y;
                int bit0 = (n & 3) * 8 + 2 * tig;
                float p0 = ((word >> bit0) & 1u) ? s[n][2 * h] : 0.f;
                float p1 = ((word >> (bit0 + 1)) & 1u) ? s[n][2 * h + 1] : 0.f;
                uint32_t h0 = f2tf32(p0), h1 = f2tf32(p1);
                int off = rloc * PAD + n * 8 + 2 * tig;
                Ph[off]     = __uint_as_float(h0);
                Ph[off + 1] = __uint_as_float(h1);
                Pl[off]     = __uint_as_float(f2tf32(p0 - __uint_as_float(h0)));
                Pl[off + 1] = __uint_as_float(f2tf32(p1 - __uint_as_float(h1)));
            }
        }
        __syncwarp();   // P rows are warp-private: STS->LDS order within warp

        // ---- PV: 2-term (ph*v + pl*v), accumulate into O regs ----
#pragma unroll
        for (int ks = 0; ks < 8; ks++) {
            uint32_t aph[4], apl[4];
            int r0 = row_base + gid;
            int c0 = ks * 8 + tig;
            aph[0] = __float_as_uint(Ph[r0 * PAD + c0]);
            aph[1] = __float_as_uint(Ph[(r0 + 8) * PAD + c0]);
            aph[2] = __float_as_uint(Ph[r0 * PAD + c0 + 4]);
            aph[3] = __float_as_uint(Ph[(r0 + 8) * PAD + c0 + 4]);
            apl[0] = __float_as_uint(Pl[r0 * PAD + c0]);
            apl[1] = __float_as_uint(Pl[(r0 + 8) * PAD + c0]);
            apl[2] = __float_as_uint(Pl[r0 * PAD + c0 + 4]);
            apl[3] = __float_as_uint(Pl[(r0 + 8) * PAD + c0 + 4]);
#pragma unroll
            for (int n = 0; n < 8; n++) {
                uint32_t b0 = __float_as_uint(Vs[(ks * 8 + tig) * PAD + n * 8 + gid]);
                uint32_t b1 = __float_as_uint(Vs[(ks * 8 + tig + 4) * PAD + n * 8 + gid]);
                mma8(o[n], aph, b0, b1);
                mma8(o[n], apl, b0, b1);
            }
        }
    }

    // ---- epilogue: O / (0.9 * l), write global ----
#pragma unroll
    for (int h = 0; h < 2; h++) {
        float inv = 1.f / (0.9f * l_[h]);
        int row = qb + row_base + gid + h * 8;
        float* Op = O + ((size_t)bh * S_ + row) * D_;
#pragma unroll
        for (int n = 0; n < 8; n++) {
            float2 v;
            v.x = o[n][2 * h] * inv;
            v.y = o[n][2 * h + 1] * inv;
            *reinterpret_cast<float2*>(Op + n * 8 + 2 * tig) = v;
        }
    }
}

// ---------------------------------------------------------------------------
extern "C" void kernel_launch(void* const* d_in, const int* in_sizes, int n_in,
                              void* d_out, int out_size) {
    (void)in_sizes; (void)n_in; (void)out_size;
    const float*    Q  = (const float*)d_in[0];
    const float*    K  = (const float*)d_in[1];
    const float*    V  = (const float*)d_in[2];
    const uint32_t* SC = (const uint32_t*)d_in[3];
    float*          O  = (float*)d_out;

    mask_kernel<<<NWORDS / 256, 256>>>();

    static const int smem = SMEM_FLOATS * (int)sizeof(float);   // 121856
    cudaFuncSetAttribute(attn_kernel,
                         cudaFuncAttributeMaxDynamicSharedMemorySize, smem);
    dim3 grid(S_ / 128, B_ * H_);
    attn_kernel<<<grid, 256, smem>>>(Q, K, V, SC, O);
}

// round 7
// speedup vs baseline: 1.6104x; 1.2445x over previous
#include <cuda_runtime.h>
#include <cstdint>

#define B_ 4
#define H_ 16
#define S_ 1024
#define D_ 64
#define NTOT   ((size_t)B_ * H_ * S_ * S_)
#define NWORDS (NTOT / 32)

__device__ uint32_t g_mask[NWORDS];   // 8 MB bitmask scratch

// ---------------------------------------------------------------------------
// Threefry-2x32, bit-exact vs JAX partitionable path (verified: rel_err 6e-8)
// ---------------------------------------------------------------------------
__device__ __forceinline__ void threefry2x32(uint32_t k0, uint32_t k1,
                                             uint32_t& x0, uint32_t& x1) {
    uint32_t ks2 = 0x1BD11BDAu ^ k0 ^ k1;
    x0 += k0; x1 += k1;
#define TF_RND(r) { x0 += x1; x1 = __funnelshift_l(x1, x1, (r)); x1 ^= x0; }
    TF_RND(13) TF_RND(15) TF_RND(26) TF_RND(6)
    x0 += k1;  x1 += ks2 + 1u;
    TF_RND(17) TF_RND(29) TF_RND(16) TF_RND(24)
    x0 += ks2; x1 += k0 + 2u;
    TF_RND(13) TF_RND(15) TF_RND(26) TF_RND(6)
    x0 += k0;  x1 += k1 + 3u;
    TF_RND(17) TF_RND(29) TF_RND(16) TF_RND(24)
    x0 += k1;  x1 += ks2 + 4u;
    TF_RND(13) TF_RND(15) TF_RND(26) TF_RND(6)
    x0 += ks2; x1 += k0 + 5u;
#undef TF_RND
}

#define KEEP_THRESH 0xE6666600u

__global__ void __launch_bounds__(256) mask_kernel() {
    uint32_t t = blockIdx.x * 256u + threadIdx.x;
    uint32_t base = t * 32u;
    uint32_t w = 0u;
#pragma unroll 4
    for (int b = 0; b < 32; b++) {
        uint32_t x0 = 0u, x1 = base + (uint32_t)b;
        threefry2x32(0u, 42u, x0, x1);
        w |= (((x0 ^ x1) < KEEP_THRESH) ? 1u : 0u) << b;
    }
    g_mask[t] = w;
}

// ---------------------------------------------------------------------------
// bf16 helpers
// ---------------------------------------------------------------------------
__device__ __forceinline__ uint32_t pack2(float lo, float hi) {
    uint32_t r;
    asm("cvt.rn.bf16x2.f32 %0, %1, %2;" : "=r"(r) : "f"(hi), "f"(lo));
    return r;
}
__device__ __forceinline__ float blo(uint32_t w) { return __uint_as_float(w << 16); }
__device__ __forceinline__ float bhi(uint32_t w) { return __uint_as_float(w & 0xffff0000u); }
// split (a,b) -> hi word + lo residual word (packed bf16x2, elem a = low half)
__device__ __forceinline__ void split2(float a, float b, uint32_t& h, uint32_t& l) {
    h = pack2(a, b);
    l = pack2(a - blo(h), b - bhi(h));
}

// d += A(bf16) * B(bf16), m16n8k16
__device__ __forceinline__ void mma16(float d[4], const uint32_t a[4],
                                      uint32_t b0, uint32_t b1) {
    asm volatile(
        "mma.sync.aligned.m16n8k16.row.col.f32.bf16.bf16.f32 "
        "{%0,%1,%2,%3}, {%4,%5,%6,%7}, {%8,%9}, {%0,%1,%2,%3};"
        : "+f"(d[0]), "+f"(d[1]), "+f"(d[2]), "+f"(d[3])
        : "r"(a[0]), "r"(a[1]), "r"(a[2]), "r"(a[3]), "r"(b0), "r"(b1));
}

#define PW 36   // word stride (bf16x2 words) -> conflict-free frag access

// word offsets. P (hi/lo) aliases the Q staging region (Q hoisted to regs).
#define W_PH 0
#define W_PL (128 * PW)
#define W_KH (2 * 128 * PW)
#define W_KL (W_KH + 64 * PW)
#define W_VH (W_KL + 64 * PW)
#define W_VL (W_VH + 64 * PW)
#define W_TOT (W_VL + 64 * PW)          // 18432 words = 73728 B

// ---------------------------------------------------------------------------
__global__ void __launch_bounds__(256, 1)
attn_kernel(const float* __restrict__ Q, const float* __restrict__ K,
            const float* __restrict__ V, const uint32_t* __restrict__ scale_ptr,
            float* __restrict__ O) {
    extern __shared__ uint32_t smw[];

    const int tid  = threadIdx.x;
    const int warp = tid >> 5;           // 0..7, owns rows [16w, 16w+16)
    const int lane = tid & 31;
    const int gid  = lane >> 2;          // 0..7
    const int tig  = lane & 3;           // 0..3
    const int bh   = blockIdx.y;
    const int qb   = blockIdx.x << 7;

    uint32_t sw = *scale_ptr;
    float scale = (sw & 0x7f800000u) ? __uint_as_float(sw) : (float)(int)sw;

    // ---- Q prologue: stage scaled hi/lo bf16x2 words, hoist frags to regs --
    {
        int r = tid >> 1, half = (tid & 1) * 32;
        const float4* Qp = reinterpret_cast<const float4*>(
            Q + ((size_t)bh * S_ + qb + r) * D_ + half);
        int wb = r * PW + (half >> 1);
#pragma unroll
        for (int i = 0; i < 8; i++) {
            float4 v = Qp[i];
            uint32_t h0, l0, h1, l1;
            split2(v.x * scale, v.y * scale, h0, l0);
            split2(v.z * scale, v.w * scale, h1, l1);
            smw[W_PH + wb + 2 * i]     = h0;
            smw[W_PH + wb + 2 * i + 1] = h1;
            smw[W_PL + wb + 2 * i]     = l0;
            smw[W_PL + wb + 2 * i + 1] = l1;
        }
    }
    __syncthreads();

    uint32_t fqh[4][4], fql[4][4];       // tile-invariant Q fragments (k16 x4)
    const int r0 = warp * 16 + gid;
    {
#pragma unroll
        for (int ks = 0; ks < 4; ks++) {
            int cb = ks * 8 + tig;
            fqh[ks][0] = smw[W_PH + r0 * PW + cb];
            fqh[ks][1] = smw[W_PH + (r0 + 8) * PW + cb];
            fqh[ks][2] = smw[W_PH + r0 * PW + cb + 4];
            fqh[ks][3] = smw[W_PH + (r0 + 8) * PW + cb + 4];
            fql[ks][0] = smw[W_PL + r0 * PW + cb];
            fql[ks][1] = smw[W_PL + (r0 + 8) * PW + cb];
            fql[ks][2] = smw[W_PL + r0 * PW + cb + 4];
            fql[ks][3] = smw[W_PL + (r0 + 8) * PW + cb + 4];
        }
    }
    __syncthreads();                     // Q staging free -> P may reuse

    float m_[2], l_[2];
    float o[8][4];
    m_[0] = m_[1] = -1e30f;
    l_[0] = l_[1] = 0.f;
#pragma unroll
    for (int n = 0; n < 8; n++)
#pragma unroll
        for (int c = 0; c < 4; c++) o[n][c] = 0.f;

    for (int t = 0; t < 16; t++) {
        // ---- prefetch dropout words ----
        uint2 mw[2];
#pragma unroll
        for (int h = 0; h < 2; h++) {
            size_t rg = (size_t)(bh * S_ + qb + r0 + 8 * h);
            mw[h] = *reinterpret_cast<const uint2*>(g_mask + (rg << 5) + t * 2);
        }

        __syncthreads();                 // prev-iter PV readers done

        // ---- K tile: thread owns 16 d-elems of one key row; split hi/lo ----
        {
            int r = tid >> 2, qv = (tid & 3) << 4;
            const float4* Kt = reinterpret_cast<const float4*>(
                K + ((size_t)bh * S_ + t * 64 + r) * D_ + qv);
            uint32_t kh[8], kl[8];
#pragma unroll
            for (int i = 0; i < 4; i++) {
                float4 v = Kt[i];
                split2(v.x, v.y, kh[2 * i],     kl[2 * i]);
                split2(v.z, v.w, kh[2 * i + 1], kl[2 * i + 1]);
            }
            int wb = r * PW + (qv >> 1);
            *reinterpret_cast<uint4*>(smw + W_KH + wb) =
                make_uint4(kh[0], kh[1], kh[2], kh[3]);
            *reinterpret_cast<uint4*>(smw + W_KH + wb + 4) =
                make_uint4(kh[4], kh[5], kh[6], kh[7]);
            *reinterpret_cast<uint4*>(smw + W_KL + wb) =
                make_uint4(kl[0], kl[1], kl[2], kl[3]);
            *reinterpret_cast<uint4*>(smw + W_KL + wb + 4) =
                make_uint4(kl[4], kl[5], kl[6], kl[7]);
        }

        // ---- V tile: transposed [d][key-pair word], split hi/lo ----
        {
            int kp = tid & 31, db = (tid >> 5) << 3;
            const float* Vb = V + ((size_t)bh * S_ + t * 64 + 2 * kp) * D_ + db;
            float4 a0 = reinterpret_cast<const float4*>(Vb)[0];
            float4 a1 = reinterpret_cast<const float4*>(Vb)[1];
            float4 b0 = reinterpret_cast<const float4*>(Vb + D_)[0];
            float4 b1 = reinterpret_cast<const float4*>(Vb + D_)[1];
            float fa[8] = {a0.x, a0.y, a0.z, a0.w, a1.x, a1.y, a1.z, a1.w};
            float fb[8] = {b0.x, b0.y, b0.z, b0.w, b1.x, b1.y, b1.z, b1.w};
#pragma unroll
            for (int i = 0; i < 8; i++) {
                uint32_t h, l;
                split2(fa[i], fb[i], h, l);    // lo=key 2kp, hi=key 2kp+1
                smw[W_VH + (db + i) * PW + kp] = h;
                smw[W_VL + (db + i) * PW + kp] = l;
            }
        }
        __syncthreads();

        // ---- QK: 3-term bf16 (qh*kh + ql*kh + qh*kl) ----
        float s[8][4];
#pragma unroll
        for (int n = 0; n < 8; n++)
#pragma unroll
            for (int c = 0; c < 4; c++) s[n][c] = 0.f;

#pragma unroll
        for (int ks = 0; ks < 4; ks++) {
            int cb = ks * 8 + tig;
#pragma unroll
            for (int n = 0; n < 8; n++) {
                int rowo = (n * 8 + gid) * PW + cb;
                uint32_t bh0 = smw[W_KH + rowo], bh1 = smw[W_KH + rowo + 4];
                uint32_t bl0 = smw[W_KL + rowo], bl1 = smw[W_KL + rowo + 4];
                mma16(s[n], fqh[ks], bh0, bh1);
                mma16(s[n], fql[ks], bh0, bh1);
                mma16(s[n], fqh[ks], bl0, bl1);
            }
        }

        // ---- online softmax (row lives on a lane quad) ----
#pragma unroll
        for (int h = 0; h < 2; h++) {
            float mx = -1e30f;
#pragma unroll
            for (int n = 0; n < 8; n++)
                mx = fmaxf(mx, fmaxf(s[n][2 * h], s[n][2 * h + 1]));
            mx = fmaxf(mx, __shfl_xor_sync(0xffffffffu, mx, 1));
            mx = fmaxf(mx, __shfl_xor_sync(0xffffffffu, mx, 2));
            float mnew = fmaxf(m_[h], mx);
            float corr = __expf(m_[h] - mnew);
            m_[h] = mnew;
            float sum = 0.f;
#pragma unroll
            for (int n = 0; n < 8; n++) {
                float e0 = __expf(s[n][2 * h] - mnew);
                float e1 = __expf(s[n][2 * h + 1] - mnew);
                s[n][2 * h] = e0;
                s[n][2 * h + 1] = e1;
                sum += e0 + e1;
            }
            sum += __shfl_xor_sync(0xffffffffu, sum, 1);
            sum += __shfl_xor_sync(0xffffffffu, sum, 2);
            l_[h] = l_[h] * corr + sum;
#pragma unroll
            for (int n = 0; n < 8; n++) {
                o[n][2 * h] *= corr;
                o[n][2 * h + 1] *= corr;
            }
        }

        // ---- dropout + P (hi/lo bf16x2) to smem ----
#pragma unroll
        for (int h = 0; h < 2; h++) {
            int rw = (r0 + 8 * h) * PW;
#pragma unroll
            for (int n = 0; n < 8; n++) {
                uint32_t word = (n < 4) ? mw[h].x : mw[h].y;
                int bit0 = (n & 3) * 8 + 2 * tig;
                float p0 = ((word >> bit0) & 1u) ? s[n][2 * h] : 0.f;
                float p1 = ((word >> (bit0 + 1)) & 1u) ? s[n][2 * h + 1] : 0.f;
                uint32_t hh, ll;
                split2(p0, p1, hh, ll);
                smw[W_PH + rw + n * 4 + tig] = hh;
                smw[W_PL + rw + n * 4 + tig] = ll;
            }
        }
        __syncwarp();   // P rows are warp-private: STS->LDS order within warp

        // ---- PV: 3-term bf16 (ph*vh + ph*vl + pl*vh) ----
#pragma unroll
        for (int ks = 0; ks < 4; ks++) {
            int cb = ks * 8 + tig;
            uint32_t aph[4], apl[4];
            aph[0] = smw[W_PH + r0 * PW + cb];
            aph[1] = smw[W_PH + (r0 + 8) * PW + cb];
            aph[2] = smw[W_PH + r0 * PW + cb + 4];
            aph[3] = smw[W_PH + (r0 + 8) * PW + cb + 4];
            apl[0] = smw[W_PL + r0 * PW + cb];
            apl[1] = smw[W_PL + (r0 + 8) * PW + cb];
            apl[2] = smw[W_PL + r0 * PW + cb + 4];
            apl[3] = smw[W_PL + (r0 + 8) * PW + cb + 4];
#pragma unroll
            for (int n = 0; n < 8; n++) {
                int rowo = (n * 8 + gid) * PW + cb;
                uint32_t vh0 = smw[W_VH + rowo], vh1 = smw[W_VH + rowo + 4];
                uint32_t vl0 = smw[W_VL + rowo], vl1 = smw[W_VL + rowo + 4];
                mma16(o[n], aph, vh0, vh1);
                mma16(o[n], aph, vl0, vl1);
                mma16(o[n], apl, vh0, vh1);
            }
        }
    }

    // ---- epilogue: O / (0.9 * l), write global ----
#pragma unroll
    for (int h = 0; h < 2; h++) {
        float inv = 1.f / (0.9f * l_[h]);
        int row = qb + r0 + h * 8;
        float* Op = O + ((size_t)bh * S_ + row) * D_;
#pragma unroll
        for (int n = 0; n < 8; n++) {
            float2 v;
            v.x = o[n][2 * h] * inv;
            v.y = o[n][2 * h + 1] * inv;
            *reinterpret_cast<float2*>(Op + n * 8 + 2 * tig) = v;
        }
    }
}

// ---------------------------------------------------------------------------
extern "C" void kernel_launch(void* const* d_in, const int* in_sizes, int n_in,
                              void* d_out, int out_size) {
    (void)in_sizes; (void)n_in; (void)out_size;
    const float*    Q  = (const float*)d_in[0];
    const float*    K  = (const float*)d_in[1];
    const float*    V  = (const float*)d_in[2];
    const uint32_t* SC = (const uint32_t*)d_in[3];
    float*          O  = (float*)d_out;

    mask_kernel<<<NWORDS / 256, 256>>>();

    const int smem = W_TOT * (int)sizeof(uint32_t);   // 73728 B
    cudaFuncSetAttribute(attn_kernel,
                         cudaFuncAttributeMaxDynamicSharedMemorySize, smem);
    dim3 grid(S_ / 128, B_ * H_);
    attn_kernel<<<grid, 256, smem>>>(Q, K, V, SC, O);
}

// round 8
// speedup vs baseline: 1.8685x; 1.1603x over previous
#include <cuda_runtime.h>
#include <cstdint>

#define B_ 4
#define H_ 16
#define S_ 1024
#define D_ 64
#define NTOT   ((size_t)B_ * H_ * S_ * S_)
#define NWORDS (NTOT / 32)

__device__ uint32_t g_mask[NWORDS];   // 8 MB bitmask scratch

// ---------------------------------------------------------------------------
// Threefry-2x32, bit-exact vs JAX partitionable path (verified: rel_err 6e-8)
// ---------------------------------------------------------------------------
__device__ __forceinline__ void threefry2x32(uint32_t k0, uint32_t k1,
                                             uint32_t& x0, uint32_t& x1) {
    uint32_t ks2 = 0x1BD11BDAu ^ k0 ^ k1;
    x0 += k0; x1 += k1;
#define TF_RND(r) { x0 += x1; x1 = __funnelshift_l(x1, x1, (r)); x1 ^= x0; }
    TF_RND(13) TF_RND(15) TF_RND(26) TF_RND(6)
    x0 += k1;  x1 += ks2 + 1u;
    TF_RND(17) TF_RND(29) TF_RND(16) TF_RND(24)
    x0 += ks2; x1 += k0 + 2u;
    TF_RND(13) TF_RND(15) TF_RND(26) TF_RND(6)
    x0 += k0;  x1 += k1 + 3u;
    TF_RND(17) TF_RND(29) TF_RND(16) TF_RND(24)
    x0 += k1;  x1 += ks2 + 4u;
    TF_RND(13) TF_RND(15) TF_RND(26) TF_RND(6)
    x0 += ks2; x1 += k0 + 5u;
#undef TF_RND
}

#define KEEP_THRESH 0xE6666600u

__global__ void __launch_bounds__(256) mask_kernel() {
    uint32_t t = blockIdx.x * 256u + threadIdx.x;
    uint32_t base = t * 32u;
    uint32_t w = 0u;
#pragma unroll 4
    for (int b = 0; b < 32; b++) {
        uint32_t x0 = 0u, x1 = base + (uint32_t)b;
        threefry2x32(0u, 42u, x0, x1);
        w |= (((x0 ^ x1) < KEEP_THRESH) ? 1u : 0u) << b;
    }
    g_mask[t] = w;
}

// ---------------------------------------------------------------------------
// bf16 helpers
// ---------------------------------------------------------------------------
__device__ __forceinline__ uint32_t pack2(float lo, float hi) {
    uint32_t r;
    asm("cvt.rn.bf16x2.f32 %0, %1, %2;" : "=r"(r) : "f"(hi), "f"(lo));
    return r;
}
__device__ __forceinline__ float blo(uint32_t w) { return __uint_as_float(w << 16); }
__device__ __forceinline__ float bhi(uint32_t w) { return __uint_as_float(w & 0xffff0000u); }
__device__ __forceinline__ void split2(float a, float b, uint32_t& h, uint32_t& l) {
    h = pack2(a, b);
    l = pack2(a - blo(h), b - bhi(h));
}

// d += A(bf16) * B(bf16), m16n8k16
__device__ __forceinline__ void mma16(float d[4], const uint32_t a[4],
                                      uint32_t b0, uint32_t b1) {
    asm volatile(
        "mma.sync.aligned.m16n8k16.row.col.f32.bf16.bf16.f32 "
        "{%0,%1,%2,%3}, {%4,%5,%6,%7}, {%8,%9}, {%0,%1,%2,%3};"
        : "+f"(d[0]), "+f"(d[1]), "+f"(d[2]), "+f"(d[3])
        : "r"(a[0]), "r"(a[1]), "r"(a[2]), "r"(a[3]), "r"(b0), "r"(b1));
}

__device__ __forceinline__ void ldm_x4(uint32_t r[4], uint32_t addr) {
    asm volatile("ldmatrix.sync.aligned.m8n8.x4.shared.b16 {%0,%1,%2,%3}, [%4];"
                 : "=r"(r[0]), "=r"(r[1]), "=r"(r[2]), "=r"(r[3]) : "r"(addr));
}

#define PW 36   // word stride: 144 B/row -> ldmatrix rows land on distinct banks

// word offsets (no aliasing; P lives in registers)
#define W_QH 0
#define W_QL (128 * PW)
#define W_KH (2 * 128 * PW)
#define W_KL (W_KH + 64 * PW)
#define W_VH (W_KL + 64 * PW)
#define W_VL (W_VH + 64 * PW)
#define W_TOT (W_VL + 64 * PW)          // 18432 words = 73728 B -> 2 CTAs/SM

// ---------------------------------------------------------------------------
__global__ void __launch_bounds__(256, 2)
attn_kernel(const float* __restrict__ Q, const float* __restrict__ K,
            const float* __restrict__ V, const uint32_t* __restrict__ scale_ptr,
            float* __restrict__ O) {
    extern __shared__ uint32_t smw[];

    const int tid  = threadIdx.x;
    const int warp = tid >> 5;           // 0..7, owns rows [16w, 16w+16)
    const int lane = tid & 31;
    const int gid  = lane >> 2;          // 0..7
    const int tig  = lane & 3;           // 0..3
    const int bh   = blockIdx.y;
    const int qb   = blockIdx.x << 7;
    const int r0   = warp * 16 + gid;

    uint32_t sw = *scale_ptr;
    float scale = (sw & 0x7f800000u) ? __uint_as_float(sw) : (float)(int)sw;

    // per-lane ldmatrix base addresses (byte, shared space)
    const uint32_t sb = (uint32_t)__cvta_generic_to_shared(smw);
    const uint32_t laneA = (uint32_t)((lane & 15) * PW + ((lane & 16) ? 4 : 0));
    const uint32_t laneBK = (uint32_t)(((lane < 16) ? W_KH : W_KL)
                                       + (lane & 7) * PW + ((lane & 8) ? 4 : 0));
    const uint32_t laneBV = (uint32_t)(((lane < 16) ? W_VH : W_VL)
                                       + (lane & 7) * PW + ((lane & 8) ? 4 : 0));
    const uint32_t aQH = sb + 4u * (W_QH + (uint32_t)(warp * 16) * PW + laneA);
    const uint32_t aQL = sb + 4u * (W_QL + (uint32_t)(warp * 16) * PW + laneA);
    const uint32_t aK  = sb + 4u * laneBK;
    const uint32_t aV  = sb + 4u * laneBV;

    // ---- Q prologue: stage scaled hi/lo bf16x2 words into smem ----
    {
        int r = tid >> 1, half = (tid & 1) * 32;
        const float4* Qp = reinterpret_cast<const float4*>(
            Q + ((size_t)bh * S_ + qb + r) * D_ + half);
        int wb = r * PW + (half >> 1);
#pragma unroll
        for (int i = 0; i < 8; i++) {
            float4 v = Qp[i];
            uint32_t h0, l0, h1, l1;
            split2(v.x * scale, v.y * scale, h0, l0);
            split2(v.z * scale, v.w * scale, h1, l1);
            smw[W_QH + wb + 2 * i]     = h0;
            smw[W_QH + wb + 2 * i + 1] = h1;
            smw[W_QL + wb + 2 * i]     = l0;
            smw[W_QL + wb + 2 * i + 1] = l1;
        }
    }

    float m_[2], l_[2];
    float o[8][4];
    m_[0] = m_[1] = -1e30f;
    l_[0] = l_[1] = 0.f;
#pragma unroll
    for (int n = 0; n < 8; n++)
#pragma unroll
        for (int c = 0; c < 4; c++) o[n][c] = 0.f;

    __syncthreads();

    for (int t = 0; t < 16; t++) {
        // ---- prefetch dropout words ----
        uint2 mw[2];
#pragma unroll
        for (int h = 0; h < 2; h++) {
            size_t rg = (size_t)(bh * S_ + qb + r0 + 8 * h);
            mw[h] = *reinterpret_cast<const uint2*>(g_mask + (rg << 5) + t * 2);
        }

        if (t) __syncthreads();          // prev-iter K/V readers done

        // ---- K tile: thread owns 16 d-elems of one key row; split hi/lo ----
        {
            int r = tid >> 2, qv = (tid & 3) << 4;
            const float4* Kt = reinterpret_cast<const float4*>(
                K + ((size_t)bh * S_ + t * 64 + r) * D_ + qv);
            uint32_t kh[8], kl[8];
#pragma unroll
            for (int i = 0; i < 4; i++) {
                float4 v = Kt[i];
                split2(v.x, v.y, kh[2 * i],     kl[2 * i]);
                split2(v.z, v.w, kh[2 * i + 1], kl[2 * i + 1]);
            }
            int wb = r * PW + (qv >> 1);
            *reinterpret_cast<uint4*>(smw + W_KH + wb) =
                make_uint4(kh[0], kh[1], kh[2], kh[3]);
            *reinterpret_cast<uint4*>(smw + W_KH + wb + 4) =
                make_uint4(kh[4], kh[5], kh[6], kh[7]);
            *reinterpret_cast<uint4*>(smw + W_KL + wb) =
                make_uint4(kl[0], kl[1], kl[2], kl[3]);
            *reinterpret_cast<uint4*>(smw + W_KL + wb + 4) =
                make_uint4(kl[4], kl[5], kl[6], kl[7]);
        }

        // ---- V tile: transposed [d][key-pair word], split hi/lo ----
        {
            int kp = tid & 31, db = (tid >> 5) << 3;
            const float* Vb = V + ((size_t)bh * S_ + t * 64 + 2 * kp) * D_ + db;
            float4 a0 = reinterpret_cast<const float4*>(Vb)[0];
            float4 a1 = reinterpret_cast<const float4*>(Vb)[1];
            float4 b0 = reinterpret_cast<const float4*>(Vb + D_)[0];
            float4 b1 = reinterpret_cast<const float4*>(Vb + D_)[1];
            float fa[8] = {a0.x, a0.y, a0.z, a0.w, a1.x, a1.y, a1.z, a1.w};
            float fb[8] = {b0.x, b0.y, b0.z, b0.w, b1.x, b1.y, b1.z, b1.w};
#pragma unroll
            for (int i = 0; i < 8; i++) {
                uint32_t h, l;
                split2(fa[i], fb[i], h, l);    // lo=key 2kp, hi=key 2kp+1
                smw[W_VH + (db + i) * PW + kp] = h;
                smw[W_VL + (db + i) * PW + kp] = l;
            }
        }
        __syncthreads();

        // ---- QK: 3-term bf16, Q via ldmatrix, K via ldmatrix.x4 ----
        float s[8][4];
#pragma unroll
        for (int n = 0; n < 8; n++)
#pragma unroll
            for (int c = 0; c < 4; c++) s[n][c] = 0.f;

#pragma unroll
        for (int ks = 0; ks < 4; ks++) {
            uint32_t qh[4], ql[4];
            ldm_x4(qh, aQH + ks * 32u);
            ldm_x4(ql, aQL + ks * 32u);
#pragma unroll
            for (int n = 0; n < 8; n++) {
                uint32_t kb[4];
                ldm_x4(kb, aK + 4u * (uint32_t)(n * 8 * PW + ks * 8));
                mma16(s[n], qh, kb[0], kb[1]);
                mma16(s[n], ql, kb[0], kb[1]);
                mma16(s[n], qh, kb[2], kb[3]);
            }
        }

        // ---- online softmax (row lives on a lane quad) ----
#pragma unroll
        for (int h = 0; h < 2; h++) {
            float mx = -1e30f;
#pragma unroll
            for (int n = 0; n < 8; n++)
                mx = fmaxf(mx, fmaxf(s[n][2 * h], s[n][2 * h + 1]));
            mx = fmaxf(mx, __shfl_xor_sync(0xffffffffu, mx, 1));
            mx = fmaxf(mx, __shfl_xor_sync(0xffffffffu, mx, 2));
            float mnew = fmaxf(m_[h], mx);
            float corr = __expf(m_[h] - mnew);
            m_[h] = mnew;
            float sum = 0.f;
#pragma unroll
            for (int n = 0; n < 8; n++) {
                float e0 = __expf(s[n][2 * h] - mnew);
                float e1 = __expf(s[n][2 * h + 1] - mnew);
                s[n][2 * h] = e0;
                s[n][2 * h + 1] = e1;
                sum += e0 + e1;
            }
            sum += __shfl_xor_sync(0xffffffffu, sum, 1);
            sum += __shfl_xor_sync(0xffffffffu, sum, 2);
            l_[h] = l_[h] * corr + sum;
#pragma unroll
            for (int n = 0; n < 8; n++) {
                o[n][2 * h] *= corr;
                o[n][2 * h + 1] *= corr;
            }
        }

        // ---- PV: dropout + pack P chunk in regs, V via ldmatrix.x4 ----
#pragma unroll
        for (int ks = 0; ks < 4; ks++) {
            uint32_t aph[4], apl[4];
#pragma unroll
            for (int q = 0; q < 4; q++) {          // q = 2*(n-2ks) + h
                int n = 2 * ks + (q >> 1);
                int h = q & 1;
                uint32_t word = (n < 4) ? mw[h].x : mw[h].y;
                int bit0 = (n & 3) * 8 + 2 * tig;
                float p0 = ((word >> bit0) & 1u) ? s[n][2 * h] : 0.f;
                float p1 = ((word >> (bit0 + 1)) & 1u) ? s[n][2 * h + 1] : 0.f;
                // a-reg index: a0=(row gid, lo-k), a1=(gid+8, lo-k),
                //              a2=(gid, hi-k),     a3=(gid+8, hi-k)
                int ar = (q >> 1) * 2 + h;         // n-low: a0/a1, n-high: a2/a3
                split2(p0, p1, aph[ar], apl[ar]);
            }
#pragma unroll
            for (int n = 0; n < 8; n++) {
                uint32_t vb[4];
                ldm_x4(vb, aV + 4u * (uint32_t)(n * 8 * PW + ks * 8));
                mma16(o[n], aph, vb[0], vb[1]);
                mma16(o[n], aph, vb[2], vb[3]);
                mma16(o[n], apl, vb[0], vb[1]);
            }
        }
    }

    // ---- epilogue: O / (0.9 * l), write global ----
#pragma unroll
    for (int h = 0; h < 2; h++) {
        float inv = 1.f / (0.9f * l_[h]);
        int row = qb + r0 + h * 8;
        float* Op = O + ((size_t)bh * S_ + row) * D_;
#pragma unroll
        for (int n = 0; n < 8; n++) {
            float2 v;
            v.x = o[n][2 * h] * inv;
            v.y = o[n][2 * h + 1] * inv;
            *reinterpret_cast<float2*>(Op + n * 8 + 2 * tig) = v;
        }
    }
}

// ---------------------------------------------------------------------------
extern "C" void kernel_launch(void* const* d_in, const int* in_sizes, int n_in,
                              void* d_out, int out_size) {
    (void)in_sizes; (void)n_in; (void)out_size;
    const float*    Q  = (const float*)d_in[0];
    const float*    K  = (const float*)d_in[1];
    const float*    V  = (const float*)d_in[2];
    const uint32_t* SC = (const uint32_t*)d_in[3];
    float*          O  = (float*)d_out;

    mask_kernel<<<NWORDS / 256, 256>>>();

    const int smem = W_TOT * (int)sizeof(uint32_t);   // 73728 B
    cudaFuncSetAttribute(attn_kernel,
                         cudaFuncAttributeMaxDynamicSharedMemorySize, smem);
    dim3 grid(S_ / 128, B_ * H_);
    attn_kernel<<<grid, 256, smem>>>(Q, K, V, SC, O);
}